// round 13
// baseline (speedup 1.0000x reference)
#include <cuda_runtime.h>

#define T_DIM 2048
#define MAX_B 8192
#define BLOCK 32
#define FULLMASK 0xffffffffu

// Single 64-bit accumulator: bits[63:16] = biased fixed-point sum (per-thread
// scale 2^20, bias 2^38 per arriving warp), bits[15:0] = arrived-warp count.
// All additions are integer -> associative -> bitwise-deterministic in any
// arrival order. Last arriver holds the grand total in-hand, stores the mean,
// resets for the next graph replay.
__device__ unsigned long long g_acc = 0ULL;

// GUARDED = 1 only for a (never-taken on this dataset) ragged tail.
template <int GUARDED>
__global__ __launch_bounds__(BLOCK)
void fused_loss_kernel(const float* __restrict__ outputs,
                       const int* __restrict__ labels,
                       float* __restrict__ out, int B) {
    const int row = blockIdx.x * BLOCK + threadIdx.x;

    float per = 0.0f;
    if (!GUARDED || row < B) {
        const float* p   = outputs + (size_t)row * T_DIM;
        const int*   lab = labels  + (size_t)row * T_DIM;

        // ---- Tier A prefetch: 16 labels + 24 outputs, 10 LDG.128 in flight ----
        const int4   l0 = __ldg((const int4*)(lab));
        const int4   l1 = __ldg((const int4*)(lab + 4));
        const int4   l2 = __ldg((const int4*)(lab + 8));
        const int4   l3 = __ldg((const int4*)(lab + 12));
        const float4 q0 = __ldg((const float4*)(p));
        const float4 q1 = __ldg((const float4*)(p + 4));
        const float4 q2 = __ldg((const float4*)(p + 8));
        const float4 q3 = __ldg((const float4*)(p + 12));
        const float4 q4 = __ldg((const float4*)(p + 16));
        const float4 q5 = __ldg((const float4*)(p + 20));

        const float pf[24] = {q0.x,q0.y,q0.z,q0.w, q1.x,q1.y,q1.z,q1.w,
                              q2.x,q2.y,q2.z,q2.w, q3.x,q3.y,q3.z,q3.w,
                              q4.x,q4.y,q4.z,q4.w, q5.x,q5.y,q5.z,q5.w};
        const int   la[16] = {l0.x,l0.y,l0.z,l0.w, l1.x,l1.y,l1.z,l1.w,
                              l2.x,l2.y,l2.z,l2.w, l3.x,l3.y,l3.z,l3.w};

        const int lab0 = la[0];
        int ind0 = T_DIM;
        #pragma unroll
        for (int k = 15; k >= 1; k--)          // descending: smallest k wins
            if (la[k] != lab0) ind0 = k;

        if (ind0 <= 15) {
            // ---- TIER A (P ~ 1 - 2^-15): prefix + full n=8 window, regs only ----
            float S = 0.f, cp = 1.f;
            float term1 = 0.f, cpw = 1.f, cpl = 1.f, pl = 0.f;
            #pragma unroll
            for (int k = 0; k < 24; k++) {
                const float pk = pf[k];
                if (k < ind0) {                         // false-alarm prefix
                    S  += (float)(k + 1) * pk * cp;
                    cp *= 1.f - pk;
                }
                if (k >= ind0 && k < ind0 + 8) {        // delay window
                    const int kk = k - ind0;
                    term1 += (float)(kk + 1) * pk * cpw;
                    if (kk == 7) { cpl = cpw; pl = pk; }
                    cpw *= 1.f - pk;
                }
            }
            const float fa = 1.f - S;
            const float dd = term1 + 72.f * cpl * (1.f - pl);   // n=8, W+1=9
            per = 0.5f * dd + 0.5f * fa;                        // ALPHA=0.5
        } else {
            // ---- TIER B (P ~ 2^-15): ONE more bulk round trip, no serial chase ----
            int4   m0 = __ldg((const int4*)(lab + 16));
            int4   m1 = __ldg((const int4*)(lab + 20));
            int4   m2 = __ldg((const int4*)(lab + 24));
            int4   m3 = __ldg((const int4*)(lab + 28));
            int4   m4 = __ldg((const int4*)(lab + 32));
            int4   m5 = __ldg((const int4*)(lab + 36));
            int4   m6 = __ldg((const int4*)(lab + 40));
            int4   m7 = __ldg((const int4*)(lab + 44));
            float4 r0 = __ldg((const float4*)(p + 24));
            float4 r1 = __ldg((const float4*)(p + 28));
            float4 r2 = __ldg((const float4*)(p + 32));
            float4 r3 = __ldg((const float4*)(p + 36));
            float4 r4 = __ldg((const float4*)(p + 40));
            float4 r5 = __ldg((const float4*)(p + 44));
            float4 r6 = __ldg((const float4*)(p + 48));
            float4 r7 = __ldg((const float4*)(p + 52));

            const int   lb[32] = {m0.x,m0.y,m0.z,m0.w, m1.x,m1.y,m1.z,m1.w,
                                  m2.x,m2.y,m2.z,m2.w, m3.x,m3.y,m3.z,m3.w,
                                  m4.x,m4.y,m4.z,m4.w, m5.x,m5.y,m5.z,m5.w,
                                  m6.x,m6.y,m6.z,m6.w, m7.x,m7.y,m7.z,m7.w};
            const float pg[32] = {r0.x,r0.y,r0.z,r0.w, r1.x,r1.y,r1.z,r1.w,
                                  r2.x,r2.y,r2.z,r2.w, r3.x,r3.y,r3.z,r3.w,
                                  r4.x,r4.y,r4.z,r4.w, r5.x,r5.y,r5.z,r5.w,
                                  r6.x,r6.y,r6.z,r6.w, r7.x,r7.y,r7.z,r7.w};

            #pragma unroll
            for (int k = 31; k >= 0; k--)
                if (lb[k] != lab0) ind0 = 16 + k;

            if (ind0 <= 47) {
                float S = 0.f, cp = 1.f;
                float term1 = 0.f, cpw = 1.f, cpl = 1.f, pl = 0.f;
                #pragma unroll
                for (int k = 0; k < 56; k++) {
                    const float pk = (k < 24) ? pf[k] : pg[k - 24];
                    if (k < ind0) {
                        S  += (float)(k + 1) * pk * cp;
                        cp *= 1.f - pk;
                    }
                    if (k >= ind0 && k < ind0 + 8) {
                        const int kk = k - ind0;
                        term1 += (float)(kk + 1) * pk * cpw;
                        if (kk == 7) { cpl = cpw; pl = pk; }
                        cpw *= 1.f - pk;
                    }
                }
                const float fa = 1.f - S;
                const float dd = term1 + 72.f * cpl * (1.f - pl);
                per = 0.5f * dd + 0.5f * fa;
            } else {
                // ---- TIER C (P ~ 2^-47): fully general, correctness only ----
                ind0 = T_DIM;
                for (int base = 48; base < T_DIM; base += 4) {
                    int4 v = __ldg((const int4*)(lab + base));
                    if (v.x != lab0) { ind0 = base;     break; }
                    if (v.y != lab0) { ind0 = base + 1; break; }
                    if (v.z != lab0) { ind0 = base + 2; break; }
                    if (v.w != lab0) { ind0 = base + 3; break; }
                }
                const bool has_change = (ind0 < T_DIM);
                const int  L = has_change ? ind0 : T_DIM;
                float S = 0.f, cp = 1.f;
                for (int k = 0; k < L; k++) {
                    const float pk = p[k];
                    S  += (float)(k + 1) * pk * cp;
                    cp *= 1.f - pk;
                }
                const float fa = 1.f - S;
                if (has_change) {
                    int n = T_DIM - ind0; if (n > 8) n = 8;
                    float cpw = 1.f, term1 = 0.f, cpl = 1.f, pl = 0.f;
                    for (int kk = 0; kk < n; kk++) {
                        const float pk = p[ind0 + kk];
                        term1 += (float)(kk + 1) * pk * cpw;
                        if (kk == n - 1) { cpl = cpw; pl = pk; }
                        cpw *= 1.f - pk;
                    }
                    const float dd = term1 + (float)n * 9.f * cpl * (1.f - pl);
                    per = 0.5f * dd + 0.5f * fa;
                } else {
                    per = fa;
                }
            }
        }
    }

    // ---- warp reduce via single HW REDUX.SUM on fixed-point int32 ----
    // per-thread scale 2^20: |per| <= ~36.5 -> warp sum < 2^31, no overflow.
    const int   fixi = __float2int_rn(per * 1048576.0f);
    const int   wsum = __reduce_add_sync(FULLMASK, fixi);

    // ---- ONE atomic per warp: sum + count packed in one 64-bit word ----
    if (threadIdx.x == 0) {
        long long fix = (long long)wsum + (1LL << 38);          // integer bias
        unsigned long long packed = ((unsigned long long)fix << 16) | 1ULL;
        unsigned long long old = atomicAdd(&g_acc, packed);
        if ((old & 0xFFFFULL) == (unsigned long long)(gridDim.x - 1)) {
            unsigned long long tot = old + packed;              // grand total in hand
            long long net = (long long)(tot >> 16) - ((long long)gridDim.x << 38);
            double sum = (double)net * (1.0 / 1048576.0);
            out[0] = (float)(sum / (double)B);
            g_acc = 0ULL;                                       // reset for replay
        }
    }
}

extern "C" void kernel_launch(void* const* d_in, const int* in_sizes, int n_in,
                              void* d_out, int out_size) {
    const float* outputs = (const float*)d_in[0];
    const int*   labels  = (const int*)d_in[1];

    int B = in_sizes[0] / T_DIM;
    if (B > MAX_B) B = MAX_B;

    if ((B & (BLOCK - 1)) == 0) {
        // exact multiple of 32 (always true here): guard-free kernel
        fused_loss_kernel<0><<<B / BLOCK, BLOCK>>>(outputs, labels,
                                                   (float*)d_out, B);
    } else {
        int blocks = (B + BLOCK - 1) / BLOCK;
        fused_loss_kernel<1><<<blocks, BLOCK>>>(outputs, labels,
                                                (float*)d_out, B);
    }
}

// round 14
// speedup vs baseline: 1.0435x; 1.0435x over previous
#include <cuda_runtime.h>

#define T_DIM 2048
#define MAX_B 8192
#define BLOCK 32
#define FULLMASK 0xffffffffu

// Single 64-bit accumulator: bits[63:16] = biased fixed-point sum (per-thread
// scale 2^20, bias 2^38 per arriving warp), bits[15:0] = arrived-warp count.
// All additions are integer -> associative -> bitwise-deterministic in any
// arrival order. Last arriver holds the grand total in-hand, stores the mean,
// resets for the next graph replay.
__device__ unsigned long long g_acc = 0ULL;

// GUARDED = 1 only for a (never-taken on this dataset) ragged tail.
template <int GUARDED>
__global__ __launch_bounds__(BLOCK)
void fused_loss_kernel(const float* __restrict__ outputs,
                       const int* __restrict__ labels,
                       float* __restrict__ out, int B) {
    const int row = blockIdx.x * BLOCK + threadIdx.x;

    float per = 0.0f;
    if (!GUARDED || row < B) {
        const float* p   = outputs + (size_t)row * T_DIM;
        const int*   lab = labels  + (size_t)row * T_DIM;

        // ---- Tier A prefetch: 16 labels + 24 outputs, 10 LDG.128 in flight ----
        const int4   l0 = __ldg((const int4*)(lab));
        const int4   l1 = __ldg((const int4*)(lab + 4));
        const int4   l2 = __ldg((const int4*)(lab + 8));
        const int4   l3 = __ldg((const int4*)(lab + 12));
        const float4 q0 = __ldg((const float4*)(p));
        const float4 q1 = __ldg((const float4*)(p + 4));
        const float4 q2 = __ldg((const float4*)(p + 8));
        const float4 q3 = __ldg((const float4*)(p + 12));
        const float4 q4 = __ldg((const float4*)(p + 16));
        const float4 q5 = __ldg((const float4*)(p + 20));

        const float pf[24] = {q0.x,q0.y,q0.z,q0.w, q1.x,q1.y,q1.z,q1.w,
                              q2.x,q2.y,q2.z,q2.w, q3.x,q3.y,q3.z,q3.w,
                              q4.x,q4.y,q4.z,q4.w, q5.x,q5.y,q5.z,q5.w};
        const int   la[16] = {l0.x,l0.y,l0.z,l0.w, l1.x,l1.y,l1.z,l1.w,
                              l2.x,l2.y,l2.z,l2.w, l3.x,l3.y,l3.z,l3.w};

        const int lab0 = la[0];
        int ind0 = T_DIM;
        #pragma unroll
        for (int k = 15; k >= 1; k--)          // descending: smallest k wins
            if (la[k] != lab0) ind0 = k;

        if (ind0 <= 15) {
            // ---- TIER A (P ~ 1 - 2^-15): prefix + full n=8 window, regs only ----
            float S = 0.f, cp = 1.f;
            float term1 = 0.f, cpw = 1.f, cpl = 1.f, pl = 0.f;
            #pragma unroll
            for (int k = 0; k < 24; k++) {
                const float pk = pf[k];
                if (k < ind0) {                         // false-alarm prefix
                    S  += (float)(k + 1) * pk * cp;
                    cp *= 1.f - pk;
                }
                if (k >= ind0 && k < ind0 + 8) {        // delay window
                    const int kk = k - ind0;
                    term1 += (float)(kk + 1) * pk * cpw;
                    if (kk == 7) { cpl = cpw; pl = pk; }
                    cpw *= 1.f - pk;
                }
            }
            const float fa = 1.f - S;
            const float dd = term1 + 72.f * cpl * (1.f - pl);   // n=8, W+1=9
            per = 0.5f * dd + 0.5f * fa;                        // ALPHA=0.5
        } else {
            // ---- TIER B (P ~ 2^-15): ONE more bulk round trip, no serial chase ----
            int4   m0 = __ldg((const int4*)(lab + 16));
            int4   m1 = __ldg((const int4*)(lab + 20));
            int4   m2 = __ldg((const int4*)(lab + 24));
            int4   m3 = __ldg((const int4*)(lab + 28));
            int4   m4 = __ldg((const int4*)(lab + 32));
            int4   m5 = __ldg((const int4*)(lab + 36));
            int4   m6 = __ldg((const int4*)(lab + 40));
            int4   m7 = __ldg((const int4*)(lab + 44));
            float4 r0 = __ldg((const float4*)(p + 24));
            float4 r1 = __ldg((const float4*)(p + 28));
            float4 r2 = __ldg((const float4*)(p + 32));
            float4 r3 = __ldg((const float4*)(p + 36));
            float4 r4 = __ldg((const float4*)(p + 40));
            float4 r5 = __ldg((const float4*)(p + 44));
            float4 r6 = __ldg((const float4*)(p + 48));
            float4 r7 = __ldg((const float4*)(p + 52));

            const int   lb[32] = {m0.x,m0.y,m0.z,m0.w, m1.x,m1.y,m1.z,m1.w,
                                  m2.x,m2.y,m2.z,m2.w, m3.x,m3.y,m3.z,m3.w,
                                  m4.x,m4.y,m4.z,m4.w, m5.x,m5.y,m5.z,m5.w,
                                  m6.x,m6.y,m6.z,m6.w, m7.x,m7.y,m7.z,m7.w};
            const float pg[32] = {r0.x,r0.y,r0.z,r0.w, r1.x,r1.y,r1.z,r1.w,
                                  r2.x,r2.y,r2.z,r2.w, r3.x,r3.y,r3.z,r3.w,
                                  r4.x,r4.y,r4.z,r4.w, r5.x,r5.y,r5.z,r5.w,
                                  r6.x,r6.y,r6.z,r6.w, r7.x,r7.y,r7.z,r7.w};

            #pragma unroll
            for (int k = 31; k >= 0; k--)
                if (lb[k] != lab0) ind0 = 16 + k;

            if (ind0 <= 47) {
                float S = 0.f, cp = 1.f;
                float term1 = 0.f, cpw = 1.f, cpl = 1.f, pl = 0.f;
                #pragma unroll
                for (int k = 0; k < 56; k++) {
                    const float pk = (k < 24) ? pf[k] : pg[k - 24];
                    if (k < ind0) {
                        S  += (float)(k + 1) * pk * cp;
                        cp *= 1.f - pk;
                    }
                    if (k >= ind0 && k < ind0 + 8) {
                        const int kk = k - ind0;
                        term1 += (float)(kk + 1) * pk * cpw;
                        if (kk == 7) { cpl = cpw; pl = pk; }
                        cpw *= 1.f - pk;
                    }
                }
                const float fa = 1.f - S;
                const float dd = term1 + 72.f * cpl * (1.f - pl);
                per = 0.5f * dd + 0.5f * fa;
            } else {
                // ---- TIER C (P ~ 2^-47): fully general, correctness only ----
                ind0 = T_DIM;
                for (int base = 48; base < T_DIM; base += 4) {
                    int4 v = __ldg((const int4*)(lab + base));
                    if (v.x != lab0) { ind0 = base;     break; }
                    if (v.y != lab0) { ind0 = base + 1; break; }
                    if (v.z != lab0) { ind0 = base + 2; break; }
                    if (v.w != lab0) { ind0 = base + 3; break; }
                }
                const bool has_change = (ind0 < T_DIM);
                const int  L = has_change ? ind0 : T_DIM;
                float S = 0.f, cp = 1.f;
                for (int k = 0; k < L; k++) {
                    const float pk = p[k];
                    S  += (float)(k + 1) * pk * cp;
                    cp *= 1.f - pk;
                }
                const float fa = 1.f - S;
                if (has_change) {
                    int n = T_DIM - ind0; if (n > 8) n = 8;
                    float cpw = 1.f, term1 = 0.f, cpl = 1.f, pl = 0.f;
                    for (int kk = 0; kk < n; kk++) {
                        const float pk = p[ind0 + kk];
                        term1 += (float)(kk + 1) * pk * cpw;
                        if (kk == n - 1) { cpl = cpw; pl = pk; }
                        cpw *= 1.f - pk;
                    }
                    const float dd = term1 + (float)n * 9.f * cpl * (1.f - pl);
                    per = 0.5f * dd + 0.5f * fa;
                } else {
                    per = fa;
                }
            }
        }
    }

    // ---- warp reduce via single HW REDUX.SUM on fixed-point int32 ----
    // per-thread scale 2^20: |per| <= ~36.5 -> warp sum < 2^31, no overflow.
    const int   fixi = __float2int_rn(per * 1048576.0f);
    const int   wsum = __reduce_add_sync(FULLMASK, fixi);

    // ---- ONE atomic per warp: sum + count packed in one 64-bit word ----
    if (threadIdx.x == 0) {
        long long fix = (long long)wsum + (1LL << 38);          // integer bias
        unsigned long long packed = ((unsigned long long)fix << 16) | 1ULL;
        unsigned long long old = atomicAdd(&g_acc, packed);
        if ((old & 0xFFFFULL) == (unsigned long long)(gridDim.x - 1)) {
            unsigned long long tot = old + packed;              // grand total in hand
            long long net = (long long)(tot >> 16) - ((long long)gridDim.x << 38);
            double sum = (double)net * (1.0 / 1048576.0);
            out[0] = (float)(sum / (double)B);
            g_acc = 0ULL;                                       // reset for replay
        }
    }
}

extern "C" void kernel_launch(void* const* d_in, const int* in_sizes, int n_in,
                              void* d_out, int out_size) {
    const float* outputs = (const float*)d_in[0];
    const int*   labels  = (const int*)d_in[1];

    int B = in_sizes[0] / T_DIM;
    if (B > MAX_B) B = MAX_B;

    if ((B & (BLOCK - 1)) == 0) {
        // exact multiple of 32 (always true here): guard-free kernel
        fused_loss_kernel<0><<<B / BLOCK, BLOCK>>>(outputs, labels,
                                                   (float*)d_out, B);
    } else {
        int blocks = (B + BLOCK - 1) / BLOCK;
        fused_loss_kernel<1><<<blocks, BLOCK>>>(outputs, labels,
                                                (float*)d_out, B);
    }
}

// round 15
// speedup vs baseline: 1.0485x; 1.0049x over previous
#include <cuda_runtime.h>

#define T_DIM 2048
#define MAX_B 8192
#define BLOCK 32
#define FULLMASK 0xffffffffu

// Single 64-bit accumulator: bits[63:16] = biased fixed-point sum (per-thread
// scale 2^20, bias 2^38 per arriving warp), bits[15:0] = arrived-warp count.
// All additions are integer -> associative -> bitwise-deterministic in any
// arrival order. Last arriver holds the grand total in-hand, stores the mean,
// resets for the next graph replay.
__device__ unsigned long long g_acc = 0ULL;

// GUARDED = 1 only for a (never-taken on this dataset) ragged tail.
template <int GUARDED>
__global__ __launch_bounds__(BLOCK)
void fused_loss_kernel(const float* __restrict__ outputs,
                       const int* __restrict__ labels,
                       float* __restrict__ out, int B) {
    const int row = blockIdx.x * BLOCK + threadIdx.x;

    float per = 0.0f;
    if (!GUARDED || row < B) {
        const float* p   = outputs + (size_t)row * T_DIM;
        const int*   lab = labels  + (size_t)row * T_DIM;

        // ---- Tier A prefetch: 16 labels + 24 outputs, 10 LDG.128 in flight ----
        const int4   l0 = __ldg((const int4*)(lab));
        const int4   l1 = __ldg((const int4*)(lab + 4));
        const int4   l2 = __ldg((const int4*)(lab + 8));
        const int4   l3 = __ldg((const int4*)(lab + 12));
        const float4 q0 = __ldg((const float4*)(p));
        const float4 q1 = __ldg((const float4*)(p + 4));
        const float4 q2 = __ldg((const float4*)(p + 8));
        const float4 q3 = __ldg((const float4*)(p + 12));
        const float4 q4 = __ldg((const float4*)(p + 16));
        const float4 q5 = __ldg((const float4*)(p + 20));

        const float pf[24] = {q0.x,q0.y,q0.z,q0.w, q1.x,q1.y,q1.z,q1.w,
                              q2.x,q2.y,q2.z,q2.w, q3.x,q3.y,q3.z,q3.w,
                              q4.x,q4.y,q4.z,q4.w, q5.x,q5.y,q5.z,q5.w};
        const int   la[16] = {l0.x,l0.y,l0.z,l0.w, l1.x,l1.y,l1.z,l1.w,
                              l2.x,l2.y,l2.z,l2.w, l3.x,l3.y,l3.z,l3.w};

        const int lab0 = la[0];
        int ind0 = T_DIM;
        #pragma unroll
        for (int k = 15; k >= 1; k--)          // descending: smallest k wins
            if (la[k] != lab0) ind0 = k;

        if (ind0 <= 15) {
            // ---- TIER A (P ~ 1 - 2^-15): prefix + full n=8 window, regs only ----
            float S = 0.f, cp = 1.f;
            float term1 = 0.f, cpw = 1.f, cpl = 1.f, pl = 0.f;
            #pragma unroll
            for (int k = 0; k < 24; k++) {
                const float pk = pf[k];
                if (k < ind0) {                         // false-alarm prefix
                    S  += (float)(k + 1) * pk * cp;
                    cp *= 1.f - pk;
                }
                if (k >= ind0 && k < ind0 + 8) {        // delay window
                    const int kk = k - ind0;
                    term1 += (float)(kk + 1) * pk * cpw;
                    if (kk == 7) { cpl = cpw; pl = pk; }
                    cpw *= 1.f - pk;
                }
            }
            const float fa = 1.f - S;
            const float dd = term1 + 72.f * cpl * (1.f - pl);   // n=8, W+1=9
            per = 0.5f * dd + 0.5f * fa;                        // ALPHA=0.5
        } else {
            // ---- TIER B (P ~ 2^-15): ONE more bulk round trip, no serial chase ----
            int4   m0 = __ldg((const int4*)(lab + 16));
            int4   m1 = __ldg((const int4*)(lab + 20));
            int4   m2 = __ldg((const int4*)(lab + 24));
            int4   m3 = __ldg((const int4*)(lab + 28));
            int4   m4 = __ldg((const int4*)(lab + 32));
            int4   m5 = __ldg((const int4*)(lab + 36));
            int4   m6 = __ldg((const int4*)(lab + 40));
            int4   m7 = __ldg((const int4*)(lab + 44));
            float4 r0 = __ldg((const float4*)(p + 24));
            float4 r1 = __ldg((const float4*)(p + 28));
            float4 r2 = __ldg((const float4*)(p + 32));
            float4 r3 = __ldg((const float4*)(p + 36));
            float4 r4 = __ldg((const float4*)(p + 40));
            float4 r5 = __ldg((const float4*)(p + 44));
            float4 r6 = __ldg((const float4*)(p + 48));
            float4 r7 = __ldg((const float4*)(p + 52));

            const int   lb[32] = {m0.x,m0.y,m0.z,m0.w, m1.x,m1.y,m1.z,m1.w,
                                  m2.x,m2.y,m2.z,m2.w, m3.x,m3.y,m3.z,m3.w,
                                  m4.x,m4.y,m4.z,m4.w, m5.x,m5.y,m5.z,m5.w,
                                  m6.x,m6.y,m6.z,m6.w, m7.x,m7.y,m7.z,m7.w};
            const float pg[32] = {r0.x,r0.y,r0.z,r0.w, r1.x,r1.y,r1.z,r1.w,
                                  r2.x,r2.y,r2.z,r2.w, r3.x,r3.y,r3.z,r3.w,
                                  r4.x,r4.y,r4.z,r4.w, r5.x,r5.y,r5.z,r5.w,
                                  r6.x,r6.y,r6.z,r6.w, r7.x,r7.y,r7.z,r7.w};

            #pragma unroll
            for (int k = 31; k >= 0; k--)
                if (lb[k] != lab0) ind0 = 16 + k;

            if (ind0 <= 47) {
                float S = 0.f, cp = 1.f;
                float term1 = 0.f, cpw = 1.f, cpl = 1.f, pl = 0.f;
                #pragma unroll
                for (int k = 0; k < 56; k++) {
                    const float pk = (k < 24) ? pf[k] : pg[k - 24];
                    if (k < ind0) {
                        S  += (float)(k + 1) * pk * cp;
                        cp *= 1.f - pk;
                    }
                    if (k >= ind0 && k < ind0 + 8) {
                        const int kk = k - ind0;
                        term1 += (float)(kk + 1) * pk * cpw;
                        if (kk == 7) { cpl = cpw; pl = pk; }
                        cpw *= 1.f - pk;
                    }
                }
                const float fa = 1.f - S;
                const float dd = term1 + 72.f * cpl * (1.f - pl);
                per = 0.5f * dd + 0.5f * fa;
            } else {
                // ---- TIER C (P ~ 2^-47): fully general, correctness only ----
                ind0 = T_DIM;
                for (int base = 48; base < T_DIM; base += 4) {
                    int4 v = __ldg((const int4*)(lab + base));
                    if (v.x != lab0) { ind0 = base;     break; }
                    if (v.y != lab0) { ind0 = base + 1; break; }
                    if (v.z != lab0) { ind0 = base + 2; break; }
                    if (v.w != lab0) { ind0 = base + 3; break; }
                }
                const bool has_change = (ind0 < T_DIM);
                const int  L = has_change ? ind0 : T_DIM;
                float S = 0.f, cp = 1.f;
                for (int k = 0; k < L; k++) {
                    const float pk = p[k];
                    S  += (float)(k + 1) * pk * cp;
                    cp *= 1.f - pk;
                }
                const float fa = 1.f - S;
                if (has_change) {
                    int n = T_DIM - ind0; if (n > 8) n = 8;
                    float cpw = 1.f, term1 = 0.f, cpl = 1.f, pl = 0.f;
                    for (int kk = 0; kk < n; kk++) {
                        const float pk = p[ind0 + kk];
                        term1 += (float)(kk + 1) * pk * cpw;
                        if (kk == n - 1) { cpl = cpw; pl = pk; }
                        cpw *= 1.f - pk;
                    }
                    const float dd = term1 + (float)n * 9.f * cpl * (1.f - pl);
                    per = 0.5f * dd + 0.5f * fa;
                } else {
                    per = fa;
                }
            }
        }
    }

    // ---- warp reduce via single HW REDUX.SUM on fixed-point int32 ----
    // per-thread scale 2^20: |per| <= ~36.5 -> warp sum < 2^31, no overflow.
    const int   fixi = __float2int_rn(per * 1048576.0f);
    const int   wsum = __reduce_add_sync(FULLMASK, fixi);

    // ---- ONE atomic per warp: sum + count packed in one 64-bit word ----
    if (threadIdx.x == 0) {
        long long fix = (long long)wsum + (1LL << 38);          // integer bias
        unsigned long long packed = ((unsigned long long)fix << 16) | 1ULL;
        unsigned long long old = atomicAdd(&g_acc, packed);
        if ((old & 0xFFFFULL) == (unsigned long long)(gridDim.x - 1)) {
            unsigned long long tot = old + packed;              // grand total in hand
            long long net = (long long)(tot >> 16) - ((long long)gridDim.x << 38);
            double sum = (double)net * (1.0 / 1048576.0);
            out[0] = (float)(sum / (double)B);
            g_acc = 0ULL;                                       // reset for replay
        }
    }
}

extern "C" void kernel_launch(void* const* d_in, const int* in_sizes, int n_in,
                              void* d_out, int out_size) {
    const float* outputs = (const float*)d_in[0];
    const int*   labels  = (const int*)d_in[1];

    int B = in_sizes[0] / T_DIM;
    if (B > MAX_B) B = MAX_B;

    if ((B & (BLOCK - 1)) == 0) {
        // exact multiple of 32 (always true here): guard-free kernel
        fused_loss_kernel<0><<<B / BLOCK, BLOCK>>>(outputs, labels,
                                                   (float*)d_out, B);
    } else {
        int blocks = (B + BLOCK - 1) / BLOCK;
        fused_loss_kernel<1><<<blocks, BLOCK>>>(outputs, labels,
                                                (float*)d_out, B);
    }
}